// round 3
// baseline (speedup 1.0000x reference)
#include <cuda_runtime.h>
#include <cuda_bf16.h>
#include <stdint.h>

// Problem constants (fixed by the reference)
#define BATCH 1024
#define IN_SIZE 2048
#define OUT_SIZE 2048
#define EMAX 131072
#define NGROUPS 64                 // output groups of 32
#define NTILES 32                  // input tiles of 64
#define NKEYS 65536                // group(6) | tile(5) | olow(5)
#define ECAP 2816                  // smem stage capacity per group (mean 2048, +17 sigma)

// -------- device scratch (no allocations allowed) --------
__device__ float g_xT[IN_SIZE * BATCH];      // 8 MB : x transposed [in][batch]
__device__ float g_outT[OUT_SIZE * BATCH];   // 8 MB : out transposed [out][batch]
__device__ int   g_cnt[NKEYS];
__device__ int   g_off[NKEYS + 1];
__device__ int   g_cur[NKEYS];
__device__ uint2 g_srt[EMAX];                // {w_bits, in_idx}
__device__ int   g_idx64;

__device__ __forceinline__ int fetch_idx(const void* p, int e, int is64) {
    if (is64) return (int)(((const long long*)p)[e]);
    return ((const int*)p)[e];
}

__device__ __forceinline__ int make_key(int o, int i) {
    return ((o >> 5) << 10) | ((i >> 6) << 5) | (o & 31);
}

// -------- 1. zero counters + detect index dtype (fused) --------
__global__ void setup_kernel(const void* in_idx, int E) {
    int t = blockIdx.x * blockDim.x + threadIdx.x;
    if (t < NKEYS) g_cnt[t] = 0;
    if (t == 0) {
        const long long* q = (const long long*)in_idx;
        int n = E < 32 ? E : 32;
        bool ok64 = true;
        for (int k = 0; k < n; k++) {
            long long v = q[k];
            if (v < 0 || v >= IN_SIZE) { ok64 = false; break; }
        }
        g_idx64 = ok64 ? 1 : 0;
    }
}

// -------- 2. histogram over composite key --------
__global__ void hist_kernel(const void* in_idx, const void* out_idx, int E) {
    int is64 = g_idx64;
    for (int e = blockIdx.x * blockDim.x + threadIdx.x; e < E;
         e += gridDim.x * blockDim.x) {
        int o = fetch_idx(out_idx, e, is64);
        int i = fetch_idx(in_idx, e, is64);
        atomicAdd(&g_cnt[make_key(o, i)], 1);
    }
}

// -------- 3. single-kernel exclusive scan of 65536 counters -----------------
// 1024 threads; each serially scans 64 consecutive counters; one block scan
// of the 1024 partial sums via shuffles.
__global__ void scan_kernel() {
    int t = threadIdx.x;
    int lane = t & 31;
    int wid = t >> 5;
    int base = t << 6;

    int s = 0;
#pragma unroll 8
    for (int i = 0; i < 64; i++) s += g_cnt[base + i];

    // block-wide inclusive scan of s
    int x = s;
#pragma unroll
    for (int d = 1; d < 32; d <<= 1) {
        int y = __shfl_up_sync(0xFFFFFFFFu, x, d);
        if (lane >= d) x += y;
    }
    __shared__ int ws[32];
    if (lane == 31) ws[wid] = x;
    __syncthreads();
    if (wid == 0) {
        int v = ws[lane];
#pragma unroll
        for (int d = 1; d < 32; d <<= 1) {
            int y = __shfl_up_sync(0xFFFFFFFFu, v, d);
            if (lane >= d) v += y;
        }
        ws[lane] = v;
    }
    __syncthreads();
    int inc = x + (wid > 0 ? ws[wid - 1] : 0);
    int run = inc - s;  // exclusive prefix for this thread's range

#pragma unroll 8
    for (int i = 0; i < 64; i++) {
        int c = g_cnt[base + i];
        g_off[base + i] = run;
        g_cur[base + i] = run;
        run += c;
    }
    if (t == 1023) g_off[NKEYS] = run;  // == E
}

// -------- 4. scatter edges into key-sorted order ----------------------------
__global__ void scatter_kernel(const void* in_idx, const void* out_idx,
                               const float* w, int E) {
    int is64 = g_idx64;
    for (int e = blockIdx.x * blockDim.x + threadIdx.x; e < E;
         e += gridDim.x * blockDim.x) {
        int o = fetch_idx(out_idx, e, is64);
        int i = fetch_idx(in_idx, e, is64);
        int pos = atomicAdd(&g_cur[make_key(o, i)], 1);
        g_srt[pos] = make_uint2(__float_as_uint(w[e]), (unsigned)i);
    }
}

// -------- 5. transpose x [B][IN] -> xT [IN][B] --------
__global__ void transpose_x_kernel(const float* __restrict__ x) {
    __shared__ float tile[32][33];
    int ix = blockIdx.x * 32 + threadIdx.x;
    int ib = blockIdx.y * 32 + threadIdx.y;
#pragma unroll
    for (int j = 0; j < 4; j++)
        tile[threadIdx.y + 8 * j][threadIdx.x] = x[(ib + 8 * j) * IN_SIZE + ix];
    __syncthreads();
    int ob = blockIdx.y * 32 + threadIdx.x;
    int oi = blockIdx.x * 32 + threadIdx.y;
#pragma unroll
    for (int j = 0; j < 4; j++)
        g_xT[(oi + 8 * j) * BATCH + ob] = tile[threadIdx.x][threadIdx.y + 8 * j];
}

// -------- 6. main SpMM ------------------------------------------------------
// Block = (group of 32 outputs) x (batch half of 512). Edges sorted by
// (group, in-tile, out). Flat cursor j walks the group's staged edge list;
// the accumulator for each bucket is LEXICALLY STATIC (macro-expanded), so
// all 32 float2 accumulators stay in registers. In-tile-of-64 ordering gives
// L1 temporal reuse on the gathers (tile working set 64 cols x 2KB = 128KB).

#define DO_OUT(S)                                                              \
    {                                                                          \
        int hi = soff[ob + S];                                                 \
        for (; j < hi; ++j) {                                                  \
            uint2 ew = se[j];                                                  \
            float2 v = *reinterpret_cast<const float2*>(                       \
                &g_xT[(ew.y << 10) + bb]);                                     \
            float w = __uint_as_float(ew.x);                                   \
            a##S.x = fmaf(w, v.x, a##S.x);                                     \
            a##S.y = fmaf(w, v.y, a##S.y);                                     \
        }                                                                      \
    }

__global__ void __launch_bounds__(256) spmm_kernel() {
    int g = blockIdx.x >> 1;        // output group
    int half = blockIdx.x & 1;      // batch half
    int t = threadIdx.x;
    int bb = (half << 9) + (t << 1);
    int gkey = g << 10;

    __shared__ uint2 se[ECAP];
    __shared__ unsigned short soff[NTILES * 32];

    int ebase = g_off[gkey];
    int eend = g_off[gkey + 1024];
    int ecount = eend - ebase;
    if (ecount > ECAP) ecount = ECAP;

    for (int k = t; k < ecount; k += 256) se[k] = g_srt[ebase + k];
    for (int k = t; k < NTILES * 32; k += 256) {
        int v = g_off[gkey + k + 1] - ebase;
        soff[k] = (unsigned short)(v > ECAP ? ECAP : v);
    }
    __syncthreads();

    float2 a0 = {0,0}, a1 = {0,0}, a2 = {0,0}, a3 = {0,0};
    float2 a4 = {0,0}, a5 = {0,0}, a6 = {0,0}, a7 = {0,0};
    float2 a8 = {0,0}, a9 = {0,0}, a10 = {0,0}, a11 = {0,0};
    float2 a12 = {0,0}, a13 = {0,0}, a14 = {0,0}, a15 = {0,0};
    float2 a16 = {0,0}, a17 = {0,0}, a18 = {0,0}, a19 = {0,0};
    float2 a20 = {0,0}, a21 = {0,0}, a22 = {0,0}, a23 = {0,0};
    float2 a24 = {0,0}, a25 = {0,0}, a26 = {0,0}, a27 = {0,0};
    float2 a28 = {0,0}, a29 = {0,0}, a30 = {0,0}, a31 = {0,0};

    int j = 0;
    for (int tl = 0; tl < NTILES; tl++) {
        int ob = tl << 5;
        DO_OUT(0)  DO_OUT(1)  DO_OUT(2)  DO_OUT(3)
        DO_OUT(4)  DO_OUT(5)  DO_OUT(6)  DO_OUT(7)
        DO_OUT(8)  DO_OUT(9)  DO_OUT(10) DO_OUT(11)
        DO_OUT(12) DO_OUT(13) DO_OUT(14) DO_OUT(15)
        DO_OUT(16) DO_OUT(17) DO_OUT(18) DO_OUT(19)
        DO_OUT(20) DO_OUT(21) DO_OUT(22) DO_OUT(23)
        DO_OUT(24) DO_OUT(25) DO_OUT(26) DO_OUT(27)
        DO_OUT(28) DO_OUT(29) DO_OUT(30) DO_OUT(31)
    }

    int obase = g << 5;
#define STORE_SLOT(S)                                                          \
    *reinterpret_cast<float2*>(&g_outT[((obase + S) << 10) + bb]) = a##S;
    STORE_SLOT(0)  STORE_SLOT(1)  STORE_SLOT(2)  STORE_SLOT(3)
    STORE_SLOT(4)  STORE_SLOT(5)  STORE_SLOT(6)  STORE_SLOT(7)
    STORE_SLOT(8)  STORE_SLOT(9)  STORE_SLOT(10) STORE_SLOT(11)
    STORE_SLOT(12) STORE_SLOT(13) STORE_SLOT(14) STORE_SLOT(15)
    STORE_SLOT(16) STORE_SLOT(17) STORE_SLOT(18) STORE_SLOT(19)
    STORE_SLOT(20) STORE_SLOT(21) STORE_SLOT(22) STORE_SLOT(23)
    STORE_SLOT(24) STORE_SLOT(25) STORE_SLOT(26) STORE_SLOT(27)
    STORE_SLOT(28) STORE_SLOT(29) STORE_SLOT(30) STORE_SLOT(31)
#undef STORE_SLOT
}

// -------- 7. transpose outT [OUT][B] -> out [B][OUT] --------
__global__ void transpose_out_kernel(float* __restrict__ out) {
    __shared__ float tile[32][33];
    int ib = blockIdx.x * 32 + threadIdx.x;
    int io = blockIdx.y * 32 + threadIdx.y;
#pragma unroll
    for (int j = 0; j < 4; j++)
        tile[threadIdx.y + 8 * j][threadIdx.x] =
            g_outT[(io + 8 * j) * BATCH + ib];
    __syncthreads();
    int oo = blockIdx.y * 32 + threadIdx.x;
    int ob = blockIdx.x * 32 + threadIdx.y;
#pragma unroll
    for (int j = 0; j < 4; j++)
        out[(ob + 8 * j) * OUT_SIZE + oo] = tile[threadIdx.x][threadIdx.y + 8 * j];
}

extern "C" void kernel_launch(void* const* d_in, const int* in_sizes, int n_in,
                              void* d_out, int out_size) {
    const float* x       = (const float*)d_in[0];
    const float* weights = (const float*)d_in[1];
    const void*  in_idx  = d_in[2];
    const void*  out_idx = d_in[3];
    float* out = (float*)d_out;
    int E = in_sizes[1];
    if (E > EMAX) E = EMAX;

    setup_kernel<<<NKEYS / 256, 256>>>(in_idx, E);
    hist_kernel<<<256, 256>>>(in_idx, out_idx, E);
    scan_kernel<<<1, 1024>>>();
    scatter_kernel<<<256, 256>>>(in_idx, out_idx, weights, E);

    {
        dim3 grid(IN_SIZE / 32, BATCH / 32);
        dim3 block(32, 8);
        transpose_x_kernel<<<grid, block>>>(x);
    }

    spmm_kernel<<<NGROUPS * 2, 256>>>();

    {
        dim3 grid(BATCH / 32, OUT_SIZE / 32);
        dim3 block(32, 8);
        transpose_out_kernel<<<grid, block>>>(out);
    }
}

// round 4
// speedup vs baseline: 7.5075x; 7.5075x over previous
#include <cuda_runtime.h>
#include <cuda_fp16.h>
#include <stdint.h>

// Problem constants (fixed by the reference)
#define BATCH 1024
#define IN_SIZE 2048
#define OUT_SIZE 2048
#define EMAX 131072

// -------- device scratch (no allocations allowed) --------
__device__ __half g_xT[IN_SIZE * BATCH];     // 4 MB : x transposed [in][batch], fp16
__device__ float  g_outT[OUT_SIZE * BATCH];  // 8 MB : out transposed [out][batch]
__device__ int    g_cnt[OUT_SIZE];
__device__ int    g_off[OUT_SIZE + 1];
__device__ int    g_cur[OUT_SIZE];
__device__ uint2  g_srt[EMAX];               // {w_bits, in_idx} sorted by out
__device__ int    g_idx64;

__device__ __forceinline__ int fetch_idx(const void* p, int e, int is64) {
    if (is64) return (int)(((const long long*)p)[e]);
    return ((const int*)p)[e];
}

// -------- 1. zero counters + detect index dtype (fused) --------
__global__ void setup_kernel(const void* in_idx, int E) {
    int t = blockIdx.x * blockDim.x + threadIdx.x;
    if (t < OUT_SIZE) g_cnt[t] = 0;
    if (t == 0) {
        const long long* q = (const long long*)in_idx;
        int n = E < 32 ? E : 32;
        bool ok64 = true;
        for (int k = 0; k < n; k++) {
            long long v = q[k];
            if (v < 0 || v >= IN_SIZE) { ok64 = false; break; }
        }
        g_idx64 = ok64 ? 1 : 0;
    }
}

// -------- 2. histogram over out_idx --------
__global__ void hist_kernel(const void* out_idx, int E) {
    int is64 = g_idx64;
    for (int e = blockIdx.x * blockDim.x + threadIdx.x; e < E;
         e += gridDim.x * blockDim.x) {
        int o = fetch_idx(out_idx, e, is64);
        atomicAdd(&g_cnt[o], 1);
    }
}

// -------- 3. single-kernel exclusive scan of 2048 counters ------------------
// 1024 threads, 2 counters each, shuffle-based block scan.
__global__ void scan_kernel() {
    int t = threadIdx.x;
    int lane = t & 31;
    int wid = t >> 5;
    int v0 = g_cnt[2 * t];
    int v1 = g_cnt[2 * t + 1];
    int s = v0 + v1;

    int x = s;
#pragma unroll
    for (int d = 1; d < 32; d <<= 1) {
        int y = __shfl_up_sync(0xFFFFFFFFu, x, d);
        if (lane >= d) x += y;
    }
    __shared__ int ws[32];
    if (lane == 31) ws[wid] = x;
    __syncthreads();
    if (wid == 0) {
        int v = ws[lane];
#pragma unroll
        for (int d = 1; d < 32; d <<= 1) {
            int y = __shfl_up_sync(0xFFFFFFFFu, v, d);
            if (lane >= d) v += y;
        }
        ws[lane] = v;
    }
    __syncthreads();
    int inc = x + (wid > 0 ? ws[wid - 1] : 0);
    int ex = inc - s;

    g_off[2 * t] = ex;
    g_off[2 * t + 1] = ex + v0;
    g_cur[2 * t] = ex;
    g_cur[2 * t + 1] = ex + v0;
    if (t == 1023) g_off[OUT_SIZE] = inc;
}

// -------- 4. scatter edges into out-sorted order ----------------------------
__global__ void scatter_kernel(const void* in_idx, const void* out_idx,
                               const float* w, int E) {
    int is64 = g_idx64;
    for (int e = blockIdx.x * blockDim.x + threadIdx.x; e < E;
         e += gridDim.x * blockDim.x) {
        int o = fetch_idx(out_idx, e, is64);
        int i = fetch_idx(in_idx, e, is64);
        int pos = atomicAdd(&g_cur[o], 1);
        g_srt[pos] = make_uint2(__float_as_uint(w[e]), (unsigned)i);
    }
}

// -------- 5. transpose x [B][IN] (fp32) -> xT [IN][B] (fp16) ----------------
__global__ void transpose_x_kernel(const float* __restrict__ x) {
    __shared__ float tile[32][33];
    int ix = blockIdx.x * 32 + threadIdx.x;
    int ib = blockIdx.y * 32 + threadIdx.y;
#pragma unroll
    for (int j = 0; j < 4; j++)
        tile[threadIdx.y + 8 * j][threadIdx.x] = x[(ib + 8 * j) * IN_SIZE + ix];
    __syncthreads();
    int ob = blockIdx.y * 32 + threadIdx.x;
    int oi = blockIdx.x * 32 + threadIdx.y;
#pragma unroll
    for (int j = 0; j < 4; j++)
        g_xT[(oi + 8 * j) * BATCH + ob] =
            __float2half_rn(tile[threadIdx.x][threadIdx.y + 8 * j]);
}

// -------- 6. main SpMM: one block per output column -------------------------
// Thread t owns 4 consecutive batch elements (one LDG.64 of 4 halves per edge).
// Edges for this output staged in 256-entry smem chunks; flat loop -> ptxas
// unrolls with high MLP. Accumulation in fp32.
__global__ void __launch_bounds__(256) spmm_kernel() {
    int o = blockIdx.x;
    int s = g_off[o];
    int e = g_off[o + 1];
    int t = threadIdx.x;

    __shared__ uint2 se[256];

    float4 acc = make_float4(0.f, 0.f, 0.f, 0.f);
    const __half* xp = g_xT + (t << 2);

    for (int base = s; base < e; base += 256) {
        int m = e - base;
        if (m > 256) m = 256;
        if (t < m) se[t] = g_srt[base + t];
        __syncthreads();
#pragma unroll 4
        for (int j = 0; j < m; j++) {
            uint2 ew = se[j];
            uint2 hv = *reinterpret_cast<const uint2*>(xp + (ew.y << 10));
            float w = __uint_as_float(ew.x);
            __half2 h0 = *reinterpret_cast<const __half2*>(&hv.x);
            __half2 h1 = *reinterpret_cast<const __half2*>(&hv.y);
            float2 f0 = __half22float2(h0);
            float2 f1 = __half22float2(h1);
            acc.x = fmaf(w, f0.x, acc.x);
            acc.y = fmaf(w, f0.y, acc.y);
            acc.z = fmaf(w, f1.x, acc.z);
            acc.w = fmaf(w, f1.y, acc.w);
        }
        __syncthreads();
    }
    *reinterpret_cast<float4*>(&g_outT[(o << 10) + (t << 2)]) = acc;
}

// -------- 7. transpose outT [OUT][B] -> out [B][OUT] ------------------------
__global__ void transpose_out_kernel(float* __restrict__ out) {
    __shared__ float tile[32][33];
    int ib = blockIdx.x * 32 + threadIdx.x;
    int io = blockIdx.y * 32 + threadIdx.y;
#pragma unroll
    for (int j = 0; j < 4; j++)
        tile[threadIdx.y + 8 * j][threadIdx.x] =
            g_outT[(io + 8 * j) * BATCH + ib];
    __syncthreads();
    int oo = blockIdx.y * 32 + threadIdx.x;
    int ob = blockIdx.x * 32 + threadIdx.y;
#pragma unroll
    for (int j = 0; j < 4; j++)
        out[(ob + 8 * j) * OUT_SIZE + oo] = tile[threadIdx.x][threadIdx.y + 8 * j];
}

extern "C" void kernel_launch(void* const* d_in, const int* in_sizes, int n_in,
                              void* d_out, int out_size) {
    const float* x       = (const float*)d_in[0];
    const float* weights = (const float*)d_in[1];
    const void*  in_idx  = d_in[2];
    const void*  out_idx = d_in[3];
    float* out = (float*)d_out;
    int E = in_sizes[1];
    if (E > EMAX) E = EMAX;

    setup_kernel<<<OUT_SIZE / 256, 256>>>(in_idx, E);
    hist_kernel<<<512, 256>>>(out_idx, E);
    scan_kernel<<<1, 1024>>>();
    scatter_kernel<<<512, 256>>>(in_idx, out_idx, weights, E);

    {
        dim3 grid(IN_SIZE / 32, BATCH / 32);
        dim3 block(32, 8);
        transpose_x_kernel<<<grid, block>>>(x);
    }

    spmm_kernel<<<OUT_SIZE, 256>>>();

    {
        dim3 grid(BATCH / 32, OUT_SIZE / 32);
        dim3 block(32, 8);
        transpose_out_kernel<<<grid, block>>>(out);
    }
}

// round 5
// speedup vs baseline: 9.2606x; 1.2335x over previous
#include <cuda_runtime.h>
#include <cuda_fp16.h>
#include <stdint.h>

// Problem constants (fixed by the reference)
#define BATCH 1024
#define IN_SIZE 2048
#define OUT_SIZE 2048
#define EMAX 131072
#define NBLK 64                      // build-phase blocks (edge chunks)
#define CHUNK (EMAX / NBLK)          // 2048 edges per chunk

// -------- device scratch (no allocations allowed) --------
__device__ __half g_xT[IN_SIZE * BATCH];     // 4 MB : x transposed [in][batch], fp16
__device__ float  g_outT[OUT_SIZE * BATCH];  // 8 MB : out transposed [out][batch]
__device__ int    g_cntM[NBLK][OUT_SIZE];    // per-chunk histograms
__device__ int    g_curM[NBLK][OUT_SIZE];    // per-(chunk,counter) start cursor
__device__ int    g_off[OUT_SIZE + 1];
__device__ uint2  g_srt[EMAX];               // {w_bits, in_idx} sorted by out
__device__ int    g_idx64;

__device__ __forceinline__ int fetch_idx(const void* p, int e, int is64) {
    if (is64) return (int)(((const long long*)p)[e]);
    return ((const int*)p)[e];
}

// -------- 1. detect index dtype (warp-parallel, one warp) --------
__global__ void setup_kernel(const void* in_idx, int E) {
    int lane = threadIdx.x;
    const long long* q = (const long long*)in_idx;
    long long v = (lane < E) ? q[lane] : 0;
    bool bad = (v < 0 || v >= IN_SIZE);
    unsigned m = __ballot_sync(0xFFFFFFFFu, bad);
    if (lane == 0) g_idx64 = (m == 0) ? 1 : 0;
}

// -------- 2. per-chunk histogram (smem atomics only) ------------------------
__global__ void __launch_bounds__(256) hist_kernel(const void* out_idx, int E) {
    __shared__ int sh[OUT_SIZE];
    int b = blockIdx.x;
    int t = threadIdx.x;
    int is64 = g_idx64;
#pragma unroll
    for (int k = t; k < OUT_SIZE; k += 256) sh[k] = 0;
    __syncthreads();
    int base = b * CHUNK;
    int end = base + CHUNK; if (end > E) end = E;
    for (int e = base + t; e < end; e += 256) {
        int o = fetch_idx(out_idx, e, is64);
        atomicAdd(&sh[o], 1);
    }
    __syncthreads();
#pragma unroll
    for (int k = t; k < OUT_SIZE; k += 256) g_cntM[b][k] = sh[k];
}

// -------- 3. scan: global offsets + per-chunk cursors (no atomics) ----------
// 1024 threads; thread t owns counters 2t, 2t+1.
__global__ void scan_kernel() {
    int t = threadIdx.x;
    int lane = t & 31;
    int wid = t >> 5;
    int o0 = 2 * t, o1 = 2 * t + 1;

    int s0 = 0, s1 = 0;
#pragma unroll 8
    for (int b = 0; b < NBLK; b++) { s0 += g_cntM[b][o0]; s1 += g_cntM[b][o1]; }
    int s = s0 + s1;

    int x = s;
#pragma unroll
    for (int d = 1; d < 32; d <<= 1) {
        int y = __shfl_up_sync(0xFFFFFFFFu, x, d);
        if (lane >= d) x += y;
    }
    __shared__ int ws[32];
    if (lane == 31) ws[wid] = x;
    __syncthreads();
    if (wid == 0) {
        int v = ws[lane];
#pragma unroll
        for (int d = 1; d < 32; d <<= 1) {
            int y = __shfl_up_sync(0xFFFFFFFFu, v, d);
            if (lane >= d) v += y;
        }
        ws[lane] = v;
    }
    __syncthreads();
    int inc = x + (wid > 0 ? ws[wid - 1] : 0);
    int ex = inc - s;

    g_off[o0] = ex;
    g_off[o1] = ex + s0;
    if (t == 1023) g_off[OUT_SIZE] = inc;

    int run0 = ex, run1 = ex + s0;
#pragma unroll 8
    for (int b = 0; b < NBLK; b++) {
        g_curM[b][o0] = run0;  run0 += g_cntM[b][o0];
        g_curM[b][o1] = run1;  run1 += g_cntM[b][o1];
    }
}

// -------- 4. scatter (smem atomics only; plain global stores) ---------------
__global__ void __launch_bounds__(256) scatter_kernel(const void* in_idx,
                                                      const void* out_idx,
                                                      const float* w, int E) {
    __shared__ int scur[OUT_SIZE];
    int b = blockIdx.x;
    int t = threadIdx.x;
    int is64 = g_idx64;
#pragma unroll
    for (int k = t; k < OUT_SIZE; k += 256) scur[k] = g_curM[b][k];
    __syncthreads();
    int base = b * CHUNK;
    int end = base + CHUNK; if (end > E) end = E;
    for (int e = base + t; e < end; e += 256) {
        int o = fetch_idx(out_idx, e, is64);
        int i = fetch_idx(in_idx, e, is64);
        int pos = atomicAdd(&scur[o], 1);
        g_srt[pos] = make_uint2(__float_as_uint(w[e]), (unsigned)i);
    }
}

// -------- 5. transpose x [B][IN] (fp32) -> xT [IN][B] (fp16) ----------------
__global__ void transpose_x_kernel(const float* __restrict__ x) {
    __shared__ float tile[32][33];
    int ix = blockIdx.x * 32 + threadIdx.x;
    int ib = blockIdx.y * 32 + threadIdx.y;
#pragma unroll
    for (int j = 0; j < 4; j++)
        tile[threadIdx.y + 8 * j][threadIdx.x] = x[(ib + 8 * j) * IN_SIZE + ix];
    __syncthreads();
    int ob = blockIdx.y * 32 + threadIdx.x;
    int oi = blockIdx.x * 32 + threadIdx.y;
#pragma unroll
    for (int j = 0; j < 4; j++)
        g_xT[(oi + 8 * j) * BATCH + ob] =
            __float2half_rn(tile[threadIdx.x][threadIdx.y + 8 * j]);
}

// -------- 6. main SpMM: one block per output column -------------------------
// Thread t owns 4 consecutive batch elements (one 8B load of 4 halves/edge).
// fp32 accumulation.
__global__ void __launch_bounds__(256) spmm_kernel() {
    int o = blockIdx.x;
    int s = g_off[o];
    int e = g_off[o + 1];
    int t = threadIdx.x;

    __shared__ uint2 se[256];

    float4 acc = make_float4(0.f, 0.f, 0.f, 0.f);
    const __half* xp = g_xT + (t << 2);

    for (int base = s; base < e; base += 256) {
        int m = e - base;
        if (m > 256) m = 256;
        if (t < m) se[t] = g_srt[base + t];
        __syncthreads();
#pragma unroll 4
        for (int j = 0; j < m; j++) {
            uint2 ew = se[j];
            uint2 hv = *reinterpret_cast<const uint2*>(xp + (ew.y << 10));
            float w = __uint_as_float(ew.x);
            __half2 h0 = *reinterpret_cast<const __half2*>(&hv.x);
            __half2 h1 = *reinterpret_cast<const __half2*>(&hv.y);
            float2 f0 = __half22float2(h0);
            float2 f1 = __half22float2(h1);
            acc.x = fmaf(w, f0.x, acc.x);
            acc.y = fmaf(w, f0.y, acc.y);
            acc.z = fmaf(w, f1.x, acc.z);
            acc.w = fmaf(w, f1.y, acc.w);
        }
        __syncthreads();
    }
    *reinterpret_cast<float4*>(&g_outT[(o << 10) + (t << 2)]) = acc;
}

// -------- 7. transpose outT [OUT][B] -> out [B][OUT] ------------------------
__global__ void transpose_out_kernel(float* __restrict__ out) {
    __shared__ float tile[32][33];
    int ib = blockIdx.x * 32 + threadIdx.x;
    int io = blockIdx.y * 32 + threadIdx.y;
#pragma unroll
    for (int j = 0; j < 4; j++)
        tile[threadIdx.y + 8 * j][threadIdx.x] =
            g_outT[(io + 8 * j) * BATCH + ib];
    __syncthreads();
    int oo = blockIdx.y * 32 + threadIdx.x;
    int ob = blockIdx.x * 32 + threadIdx.y;
#pragma unroll
    for (int j = 0; j < 4; j++)
        out[(ob + 8 * j) * OUT_SIZE + oo] = tile[threadIdx.x][threadIdx.y + 8 * j];
}

extern "C" void kernel_launch(void* const* d_in, const int* in_sizes, int n_in,
                              void* d_out, int out_size) {
    const float* x       = (const float*)d_in[0];
    const float* weights = (const float*)d_in[1];
    const void*  in_idx  = d_in[2];
    const void*  out_idx = d_in[3];
    float* out = (float*)d_out;
    int E = in_sizes[1];
    if (E > EMAX) E = EMAX;

    setup_kernel<<<1, 32>>>(in_idx, E);
    hist_kernel<<<NBLK, 256>>>(out_idx, E);
    scan_kernel<<<1, 1024>>>();
    scatter_kernel<<<NBLK, 256>>>(in_idx, out_idx, weights, E);

    {
        dim3 grid(IN_SIZE / 32, BATCH / 32);
        dim3 block(32, 8);
        transpose_x_kernel<<<grid, block>>>(x);
    }

    spmm_kernel<<<OUT_SIZE, 256>>>();

    {
        dim3 grid(BATCH / 32, OUT_SIZE / 32);
        dim3 block(32, 8);
        transpose_out_kernel<<<grid, block>>>(out);
    }
}